// round 14
// baseline (speedup 1.0000x reference)
#include <cuda_runtime.h>
#include <cuda_fp16.h>
#include <cstdint>

#define BB 4
#define SS 2048
#define DD 1024
#define HH 16
#define DK 64
#define M_TOT (BB*SS)   // 8192

// fp16 scratch (allocation-free rule: __device__ globals)
__device__ __half g_Q[BB*HH*SS*DK];
__device__ __half g_K[BB*HH*SS*DK];
__device__ __half g_V[BB*HH*SS*DK];
__device__ __half g_Ct[(size_t)M_TOT*DD];
__device__ __half g_Xh[(size_t)M_TOT*DD];
__device__ __half g_Wh[3*(size_t)DD*DD];         // Wq|Wk|Wv: [z][d][h*64+k]
__device__ __half g_Woh[(size_t)DD*DD];

#define QSC_F (0.125f * 1.4426950408889634f)

// ---------------------------------------------------------------------------
// helpers
// ---------------------------------------------------------------------------
__device__ __forceinline__ float fast_ex2(float x) {
    float y;
    asm("ex2.approx.ftz.f32 %0, %1;" : "=f"(y) : "f"(x));
    return y;
}

__device__ __forceinline__ void mma_f16(float* c, const uint32_t* a, uint32_t b0, uint32_t b1) {
    asm volatile(
        "mma.sync.aligned.m16n8k16.row.col.f32.f16.f16.f32 "
        "{%0,%1,%2,%3}, {%4,%5,%6,%7}, {%8,%9}, {%0,%1,%2,%3};"
        : "+f"(c[0]), "+f"(c[1]), "+f"(c[2]), "+f"(c[3])
        : "r"(a[0]), "r"(a[1]), "r"(a[2]), "r"(a[3]), "r"(b0), "r"(b1));
}

__device__ __forceinline__ void ldsm4(uint32_t* r, uint32_t addr) {
    asm volatile("ldmatrix.sync.aligned.m8n8.x4.shared.b16 {%0,%1,%2,%3}, [%4];"
        : "=r"(r[0]), "=r"(r[1]), "=r"(r[2]), "=r"(r[3]) : "r"(addr));
}
__device__ __forceinline__ void ldsm4t(uint32_t* r, uint32_t addr) {
    asm volatile("ldmatrix.sync.aligned.m8n8.x4.trans.shared.b16 {%0,%1,%2,%3}, [%4];"
        : "=r"(r[0]), "=r"(r[1]), "=r"(r[2]), "=r"(r[3]) : "r"(addr));
}

__device__ __forceinline__ uint32_t smem_u32(const void* p) {
    uint32_t a;
    asm("{ .reg .u64 t; cvta.to.shared.u64 t, %1; cvt.u32.u64 %0, t; }" : "=r"(a) : "l"(p));
    return a;
}

__device__ __forceinline__ uint32_t h2pack(float a, float b) {
    __half2 h = __floats2half2_rn(a, b);
    return *reinterpret_cast<uint32_t*>(&h);
}

#define CP16(dst, src) \
    asm volatile("cp.async.cg.shared.global [%0], [%1], 16;" :: "r"(dst), "l"(src))
#define CP_COMMIT() asm volatile("cp.async.commit_group;")
#define CP_WAIT1()  asm volatile("cp.async.wait_group 1;")
#define CP_WAIT0()  asm volatile("cp.async.wait_group 0;")

// ---------------------------------------------------------------------------
// Pre-convert kernels
// ---------------------------------------------------------------------------
__global__ __launch_bounds__(256) void conv_x(const float* __restrict__ x)
{
    const size_t i = ((size_t)blockIdx.x * 256 + threadIdx.x) * 8;
    float4 a = *reinterpret_cast<const float4*>(x + i);
    float4 b = *reinterpret_cast<const float4*>(x + i + 4);
    uint4 t;
    t.x = h2pack(a.x, a.y); t.y = h2pack(a.z, a.w);
    t.z = h2pack(b.x, b.y); t.w = h2pack(b.z, b.w);
    *reinterpret_cast<uint4*>(g_Xh + i) = t;
}

__global__ __launch_bounds__(256) void conv_w(
    const float* __restrict__ Wq, const float* __restrict__ Wk,
    const float* __restrict__ Wv, const float* __restrict__ Wo)
{
    const size_t gi = ((size_t)blockIdx.x * 256 + threadIdx.x) * 2;
    const int z = (int)(gi >> 20);
    const size_t i = gi & 1048575u;
    if (z < 3) {
        const float* src = (z == 0) ? Wq : (z == 1) ? Wk : Wv;
        float2 v = *reinterpret_cast<const float2*>(src + i);
        const int h = (int)(i >> 16);
        const int d = (int)((i >> 6) & 1023);
        const int k = (int)(i & 63);
        *reinterpret_cast<uint32_t*>(&g_Wh[(size_t)z * DD * DD + (size_t)d * DD + h * 64 + k]) =
            h2pack(v.x, v.y);
    } else {
        float2 v = *reinterpret_cast<const float2*>(Wo + i);
        *reinterpret_cast<uint32_t*>(&g_Woh[i]) = h2pack(v.x, v.y);
    }
}

// ---------------------------------------------------------------------------
// fp16 GEMM: C[128x128], BK=32, 256 thr, warp 64x32, 3-stage cp.async,
// single __syncthreads per k-iteration.
// A[m][k] pitch 40; B[k][n] pitch 136 (ldsm.trans).
// ---------------------------------------------------------------------------
#define APH 40
#define BPH 136
#define AS_BYTES (128 * APH * 2)
#define BS_BYTES (32 * BPH * 2)
#define GEMM_SMEM (3 * (AS_BYTES + BS_BYTES))
#define NKIT (DD / 32)

// MODE 0: qkv epilogue ([B,H,S,64], Q scaled).  MODE 1: fp32 out.
template<int MODE>
__device__ __forceinline__ void gemm_body(
    const __half* __restrict__ Asrc,   // [*, DD] row-major
    const __half* __restrict__ Bsrc,   // [DD, DD] row-major (z-slab base)
    int m0, int n0g, float* outp)
{
    extern __shared__ __align__(16) char sm[];
    const uint32_t as_b0 = smem_u32(sm);
    const uint32_t bs_b0 = as_b0 + 3 * AS_BYTES;

    const int nloc = n0g & 1023;

    const int tid  = threadIdx.x;
    const int warp = tid >> 5;
    const int lane = tid & 31;
    const int g    = lane >> 2;
    const int tig  = lane & 3;
    const int wm   = (warp & 1) * 64;
    const int wn   = (warp >> 1) * 32;

    const int rA  = (lane & 7) + ((lane >> 3) & 1) * 8;
    const int cA  = ((lane >> 4) & 1) * 8;
    const int rBt = (lane & 7) + ((lane >> 3) & 1) * 8;
    const int cBt = ((lane >> 4) & 1) * 8;

    const int am  = tid & 127;
    const int akh = (tid >> 7) * 16;
    const int bkr = tid >> 3;
    const int bc0 = (tid & 7) * 8;

    const uint32_t aDst = as_b0 + (am * APH + akh) * 2;
    const uint32_t bDst = bs_b0 + (bkr * BPH + bc0) * 2;
    const __half* aSrc = Asrc + (size_t)(m0 + am) * DD + akh;
    const __half* bSrc = Bsrc + (size_t)bkr * DD + nloc + bc0;

    float acc[4][4][4];
    #pragma unroll
    for (int i = 0; i < 4; ++i)
        #pragma unroll
        for (int j = 0; j < 4; ++j)
            #pragma unroll
            for (int l2 = 0; l2 < 4; ++l2) acc[i][j][l2] = 0.f;

    // prologue: tiles 0,1 -> bufs 0,1
    CP16(aDst,                    aSrc);
    CP16(aDst + 16,               aSrc + 8);
    CP16(bDst,                    bSrc);
    CP16(bDst + 128,              bSrc + 64);
    CP_COMMIT();
    CP16(aDst + AS_BYTES,         aSrc + 32);
    CP16(aDst + AS_BYTES + 16,    aSrc + 40);
    CP16(bDst + BS_BYTES,         bSrc + 32 * DD);
    CP16(bDst + BS_BYTES + 128,   bSrc + 32 * DD + 64);
    CP_COMMIT();

    int bc_ = 0;   // buffer of current tile
    int bn_ = 2;   // buffer for tile it+2

    for (int it = 0; it < NKIT; ++it) {
        if (it + 1 < NKIT) { CP_WAIT1(); } else { CP_WAIT0(); }
        __syncthreads();   // tile it visible; all warps done with tile it-1's buffer

        if (it + 2 < NKIT) {
            const uint32_t ab = (uint32_t)bn_ * AS_BYTES;
            const uint32_t bb = (uint32_t)bn_ * BS_BYTES;
            const __half* as2 = aSrc + (it + 2) * 32;
            const __half* bs2 = bSrc + (size_t)(it + 2) * 32 * DD;
            CP16(aDst + ab,       as2);
            CP16(aDst + ab + 16,  as2 + 8);
            CP16(bDst + bb,       bs2);
            CP16(bDst + bb + 128, bs2 + 64);
            CP_COMMIT();
        }

        const uint32_t asb = as_b0 + (uint32_t)bc_ * AS_BYTES;
        const uint32_t bsb = bs_b0 + (uint32_t)bc_ * BS_BYTES;
        #pragma unroll
        for (int kc = 0; kc < 2; ++kc) {
            uint32_t af[4][4];
            #pragma unroll
            for (int mt = 0; mt < 4; ++mt)
                ldsm4(af[mt], asb + ((wm + mt * 16 + rA) * APH + kc * 16 + cA) * 2);
            uint32_t bf[2][4];
            ldsm4t(bf[0], bsb + ((kc * 16 + rBt) * BPH + wn + cBt) * 2);
            ldsm4t(bf[1], bsb + ((kc * 16 + rBt) * BPH + wn + 16 + cBt) * 2);
            #pragma unroll
            for (int mt = 0; mt < 4; ++mt) {
                mma_f16(acc[mt][0], af[mt], bf[0][0], bf[0][1]);
                mma_f16(acc[mt][1], af[mt], bf[0][2], bf[0][3]);
                mma_f16(acc[mt][2], af[mt], bf[1][0], bf[1][1]);
                mma_f16(acc[mt][3], af[mt], bf[1][2], bf[1][3]);
            }
        }

        bc_ = (bc_ == 2) ? 0 : bc_ + 1;
        bn_ = (bn_ == 2) ? 0 : bn_ + 1;
    }

    // Epilogue
    if (MODE == 0) {
        const int z = n0g >> 10;
        __half* Cout = (z == 0) ? g_Q : (z == 1) ? g_K : g_V;
        const float outsc = (z == 0) ? QSC_F : 1.0f;
        #pragma unroll
        for (int mt = 0; mt < 4; ++mt) {
            #pragma unroll
            for (int nt = 0; nt < 4; ++nt) {
                const int nl = nloc + wn + nt * 8 + 2 * tig;
                const int h = nl >> 6;
                const int k = nl & 63;
                #pragma unroll
                for (int rh = 0; rh < 2; ++rh) {
                    const int m = m0 + wm + mt * 16 + g + rh * 8;
                    const int b = m >> 11;
                    const int s = m & 2047;
                    uint32_t v = h2pack(acc[mt][nt][rh * 2] * outsc, acc[mt][nt][rh * 2 + 1] * outsc);
                    *reinterpret_cast<uint32_t*>(
                        &Cout[(((size_t)(b * HH + h)) * SS + s) * DK + k]) = v;
                }
            }
        }
    } else {
        #pragma unroll
        for (int mt = 0; mt < 4; ++mt) {
            #pragma unroll
            for (int nt = 0; nt < 4; ++nt) {
                const int col = n0g + wn + nt * 8 + 2 * tig;
                #pragma unroll
                for (int rh = 0; rh < 2; ++rh) {
                    const int m = m0 + wm + mt * 16 + g + rh * 8;
                    float2 v = make_float2(acc[mt][nt][rh * 2], acc[mt][nt][rh * 2 + 1]);
                    *reinterpret_cast<float2*>(&outp[(size_t)m * DD + col]) = v;
                }
            }
        }
    }
}

__global__ __launch_bounds__(256, 2) void qkv_gemm_t()
{
    const int n0g = blockIdx.y * 128;
    const int z = n0g >> 10;
    gemm_body<0>(g_Xh, g_Wh + (size_t)z * DD * DD, blockIdx.x * 128, n0g, nullptr);
}

__global__ __launch_bounds__(256, 2) void out_gemm_t(float* __restrict__ out)
{
    gemm_body<1>(g_Ct, g_Woh, blockIdx.x * 128, blockIdx.y * 128, out);
}

// ---------------------------------------------------------------------------
// Flash attention: register P, 3-stage cp.async K/V, single sync per tile.
// Dynamic smem: K bufs [0,3), V bufs [3,6), each 64*FPH halfs.
// ---------------------------------------------------------------------------
#define FPH 72
#define KVB_BYTES (64 * FPH * 2)
#define FA_SMEM (6 * KVB_BYTES)
#define NTILE (SS / 64)

__global__ __launch_bounds__(256, 2) void flash_attn_t()
{
    extern __shared__ __align__(16) char fsm[];
    __half* KV = reinterpret_cast<__half*>(fsm);
    const uint32_t kv_b = smem_u32(fsm);

    const int tid  = threadIdx.x;
    const int w    = tid >> 5;
    const int lane = tid & 31;
    const int g    = lane >> 2;
    const int tig  = lane & 3;
    const int wr   = w * 16;

    const int rA  = (lane & 7) + ((lane >> 3) & 1) * 8;
    const int cA  = ((lane >> 4) & 1) * 8;
    const int rBn = ((lane >> 4) & 1) * 8 + (lane & 7);
    const int cBn = ((lane >> 3) & 1) * 8;
    const int rBt = (lane & 7) + ((lane >> 3) & 1) * 8;
    const int cBt = ((lane >> 4) & 1) * 8;

    const int q0 = blockIdx.x * 128;
    const int bh = blockIdx.y;
    const __half* Qp = g_Q + (size_t)bh * SS * DK;
    const __half* Kp = g_K + (size_t)bh * SS * DK;
    const __half* Vp = g_V + (size_t)bh * SS * DK;

    // stage Q across K bufs 0+1 (128 rows), read qf, release
    {
        const int qr = tid >> 1;
        const int qc = (tid & 1) * 32;
        const uint4* src = reinterpret_cast<const uint4*>(Qp + (size_t)(q0 + qr) * DK + qc);
        #pragma unroll
        for (int j = 0; j < 4; ++j)
            *reinterpret_cast<uint4*>(&KV[qr * FPH + qc + 8 * j]) = src[j];
    }
    __syncthreads();

    uint32_t qf[4][4];
    #pragma unroll
    for (int kc = 0; kc < 4; ++kc)
        ldsm4(qf[kc], kv_b + ((wr + rA) * FPH + kc * 16 + cA) * 2);
    __syncthreads();   // qf read complete before prefetch overwrites

    float of[8][4];
    #pragma unroll
    for (int nt = 0; nt < 8; ++nt)
        #pragma unroll
        for (int i = 0; i < 4; ++i) of[nt][i] = 0.f;
    float mA = -1e30f, mB = -1e30f, lA = 0.f, lB = 0.f;

    const int ls = tid >> 2;
    const int lc = (tid & 3) * 16;
    const uint32_t kDst = kv_b + (ls * FPH + lc) * 2;
    const uint32_t vDst = kv_b + 3 * KVB_BYTES + (ls * FPH + lc) * 2;
    const __half* kSrc = Kp + (size_t)ls * DK + lc;
    const __half* vSrc = Vp + (size_t)ls * DK + lc;

    // prologue: tiles 0,1 -> bufs 0,1
    CP16(kDst,                  kSrc);
    CP16(kDst + 16,             kSrc + 8);
    CP16(vDst,                  vSrc);
    CP16(vDst + 16,             vSrc + 8);
    CP_COMMIT();
    CP16(kDst + KVB_BYTES,      kSrc + 64 * DK);
    CP16(kDst + KVB_BYTES + 16, kSrc + 64 * DK + 8);
    CP16(vDst + KVB_BYTES,      vSrc + 64 * DK);
    CP16(vDst + KVB_BYTES + 16, vSrc + 64 * DK + 8);
    CP_COMMIT();

    int bc_ = 0;
    int bn_ = 2;

    for (int it = 0; it < NTILE; ++it) {
        if (it + 1 < NTILE) { CP_WAIT1(); } else { CP_WAIT0(); }
        __syncthreads();   // tile it visible; all warps done with tile it-1's buffer

        if (it + 2 < NTILE) {
            const uint32_t bo = (uint32_t)bn_ * KVB_BYTES;
            const __half* ks2 = kSrc + (size_t)(it + 2) * 64 * DK;
            const __half* vs2 = vSrc + (size_t)(it + 2) * 64 * DK;
            CP16(kDst + bo,      ks2);
            CP16(kDst + bo + 16, ks2 + 8);
            CP16(vDst + bo,      vs2);
            CP16(vDst + bo + 16, vs2 + 8);
            CP_COMMIT();
        }

        const uint32_t ksb = kv_b + (uint32_t)bc_ * KVB_BYTES;
        const uint32_t vsb = kv_b + 3 * KVB_BYTES + (uint32_t)bc_ * KVB_BYTES;

        // ---- S = Q K^T ----
        float sf[8][4];
        #pragma unroll
        for (int nt = 0; nt < 8; ++nt)
            #pragma unroll
            for (int i = 0; i < 4; ++i) sf[nt][i] = 0.f;
        #pragma unroll
        for (int kc = 0; kc < 4; ++kc) {
            #pragma unroll
            for (int ntp = 0; ntp < 4; ++ntp) {
                uint32_t bf[4];
                ldsm4(bf, ksb + ((ntp * 16 + rBn) * FPH + kc * 16 + cBn) * 2);
                mma_f16(sf[2 * ntp + 0], qf[kc], bf[0], bf[1]);
                mma_f16(sf[2 * ntp + 1], qf[kc], bf[2], bf[3]);
            }
        }

        // ---- online softmax ----
        float mtA = sf[0][0], mtB = sf[0][2];
        #pragma unroll
        for (int nt = 0; nt < 8; ++nt) {
            mtA = fmaxf(mtA, fmaxf(sf[nt][0], sf[nt][1]));
            mtB = fmaxf(mtB, fmaxf(sf[nt][2], sf[nt][3]));
        }
        mtA = fmaxf(mtA, __shfl_xor_sync(0xffffffffu, mtA, 1));
        mtA = fmaxf(mtA, __shfl_xor_sync(0xffffffffu, mtA, 2));
        mtB = fmaxf(mtB, __shfl_xor_sync(0xffffffffu, mtB, 1));
        mtB = fmaxf(mtB, __shfl_xor_sync(0xffffffffu, mtB, 2));

        const float mnA = fmaxf(mA, mtA);
        const float mnB = fmaxf(mB, mtB);

        float sumA = 0.f, sumB = 0.f;
        #pragma unroll
        for (int nt = 0; nt < 8; ++nt) {
            sf[nt][0] = fast_ex2(sf[nt][0] - mnA);
            sf[nt][1] = fast_ex2(sf[nt][1] - mnA);
            sf[nt][2] = fast_ex2(sf[nt][2] - mnB);
            sf[nt][3] = fast_ex2(sf[nt][3] - mnB);
            sumA += sf[nt][0] + sf[nt][1];
            sumB += sf[nt][2] + sf[nt][3];
        }
        sumA += __shfl_xor_sync(0xffffffffu, sumA, 1);
        sumA += __shfl_xor_sync(0xffffffffu, sumA, 2);
        sumB += __shfl_xor_sync(0xffffffffu, sumB, 1);
        sumB += __shfl_xor_sync(0xffffffffu, sumB, 2);

        const bool keep = __all_sync(0xffffffffu, (mnA == mA) & (mnB == mB));
        if (!keep) {
            const float corA = fast_ex2(mA - mnA);
            const float corB = fast_ex2(mB - mnB);
            lA = lA * corA; lB = lB * corB;
            #pragma unroll
            for (int nt = 0; nt < 8; ++nt) {
                of[nt][0] *= corA; of[nt][1] *= corA;
                of[nt][2] *= corB; of[nt][3] *= corB;
            }
        }
        lA += sumA; lB += sumB;
        mA = mnA; mB = mnB;

        // ---- P: register repack ----
        uint32_t pf[4][4];
        #pragma unroll
        for (int kc = 0; kc < 4; ++kc) {
            pf[kc][0] = h2pack(sf[2 * kc][0],     sf[2 * kc][1]);
            pf[kc][1] = h2pack(sf[2 * kc][2],     sf[2 * kc][3]);
            pf[kc][2] = h2pack(sf[2 * kc + 1][0], sf[2 * kc + 1][1]);
            pf[kc][3] = h2pack(sf[2 * kc + 1][2], sf[2 * kc + 1][3]);
        }

        // ---- O += P V ----
        #pragma unroll
        for (int kc = 0; kc < 4; ++kc) {
            #pragma unroll
            for (int ntp = 0; ntp < 4; ++ntp) {
                uint32_t bf[4];
                ldsm4t(bf, vsb + ((kc * 16 + rBt) * FPH + ntp * 16 + cBt) * 2);
                mma_f16(of[2 * ntp + 0], pf[kc], bf[0], bf[1]);
                mma_f16(of[2 * ntp + 1], pf[kc], bf[2], bf[3]);
            }
        }

        bc_ = (bc_ == 2) ? 0 : bc_ + 1;
        bn_ = (bn_ == 2) ? 0 : bn_ + 1;
    }

    // ---- epilogue ----
    {
        const float invA = 1.f / lA;
        const float invB = 1.f / lB;
        const int b = bh >> 4, h = bh & 15;
        const size_t rowA = (size_t)b * SS + q0 + wr + g;
        const size_t rowB = rowA + 8;
        #pragma unroll
        for (int nt = 0; nt < 8; ++nt) {
            const int col = h * 64 + nt * 8 + 2 * tig;
            *reinterpret_cast<uint32_t*>(&g_Ct[rowA * DD + col]) =
                h2pack(of[nt][0] * invA, of[nt][1] * invA);
            *reinterpret_cast<uint32_t*>(&g_Ct[rowB * DD + col]) =
                h2pack(of[nt][2] * invB, of[nt][3] * invB);
        }
    }
}

extern "C" void kernel_launch(void* const* d_in, const int* in_sizes, int n_in,
                              void* d_out, int out_size)
{
    const float* x  = (const float*)d_in[0];
    const float* Wq = (const float*)d_in[1];
    const float* Wk = (const float*)d_in[2];
    const float* Wv = (const float*)d_in[3];
    const float* Wo = (const float*)d_in[4];
    float* out = (float*)d_out;

    (void)in_sizes; (void)n_in; (void)out_size;

    cudaFuncSetAttribute(qkv_gemm_t, cudaFuncAttributeMaxDynamicSharedMemorySize, GEMM_SMEM);
    cudaFuncSetAttribute(out_gemm_t, cudaFuncAttributeMaxDynamicSharedMemorySize, GEMM_SMEM);
    cudaFuncSetAttribute(flash_attn_t, cudaFuncAttributeMaxDynamicSharedMemorySize, FA_SMEM);

    conv_x<<<(M_TOT * DD) / (256 * 8), 256>>>(x);
    conv_w<<<(4 * DD * DD) / (256 * 2), 256>>>(Wq, Wk, Wv, Wo);
    qkv_gemm_t<<<dim3(M_TOT / 128, 24), 256, GEMM_SMEM>>>();
    flash_attn_t<<<dim3(SS / 128, BB * HH), 256, FA_SMEM>>>();
    out_gemm_t<<<dim3(M_TOT / 128, 8), 256, GEMM_SMEM>>>(out);
}

// round 15
// speedup vs baseline: 1.0207x; 1.0207x over previous
#include <cuda_runtime.h>
#include <cuda_fp16.h>
#include <cstdint>

#define BB 4
#define SS 2048
#define DD 1024
#define HH 16
#define DK 64
#define M_TOT (BB*SS)   // 8192

// fp16 scratch (allocation-free rule: __device__ globals)
__device__ __half g_Q[BB*HH*SS*DK];
__device__ __half g_K[BB*HH*SS*DK];
__device__ __half g_V[BB*HH*SS*DK];
__device__ __half g_Ct[(size_t)M_TOT*DD];
__device__ __half g_Xh[(size_t)M_TOT*DD];
__device__ __half g_Wh[3*(size_t)DD*DD];         // Wq|Wk|Wv: [z][d][h*64+k]
__device__ __half g_Woh[(size_t)DD*DD];

#define QSC_F (0.125f * 1.4426950408889634f)

// ---------------------------------------------------------------------------
// helpers
// ---------------------------------------------------------------------------
__device__ __forceinline__ float fast_ex2(float x) {
    float y;
    asm("ex2.approx.ftz.f32 %0, %1;" : "=f"(y) : "f"(x));
    return y;
}

__device__ __forceinline__ uint32_t ex2_h2(uint32_t x) {
    uint32_t y;
    asm("ex2.approx.f16x2 %0, %1;" : "=r"(y) : "r"(x));
    return y;
}

__device__ __forceinline__ void mma_f16(float* c, const uint32_t* a, uint32_t b0, uint32_t b1) {
    asm volatile(
        "mma.sync.aligned.m16n8k16.row.col.f32.f16.f16.f32 "
        "{%0,%1,%2,%3}, {%4,%5,%6,%7}, {%8,%9}, {%0,%1,%2,%3};"
        : "+f"(c[0]), "+f"(c[1]), "+f"(c[2]), "+f"(c[3])
        : "r"(a[0]), "r"(a[1]), "r"(a[2]), "r"(a[3]), "r"(b0), "r"(b1));
}

__device__ __forceinline__ void ldsm4(uint32_t* r, uint32_t addr) {
    asm volatile("ldmatrix.sync.aligned.m8n8.x4.shared.b16 {%0,%1,%2,%3}, [%4];"
        : "=r"(r[0]), "=r"(r[1]), "=r"(r[2]), "=r"(r[3]) : "r"(addr));
}
__device__ __forceinline__ void ldsm4t(uint32_t* r, uint32_t addr) {
    asm volatile("ldmatrix.sync.aligned.m8n8.x4.trans.shared.b16 {%0,%1,%2,%3}, [%4];"
        : "=r"(r[0]), "=r"(r[1]), "=r"(r[2]), "=r"(r[3]) : "r"(addr));
}

__device__ __forceinline__ uint32_t smem_u32(const void* p) {
    uint32_t a;
    asm("{ .reg .u64 t; cvta.to.shared.u64 t, %1; cvt.u32.u64 %0, t; }" : "=r"(a) : "l"(p));
    return a;
}

__device__ __forceinline__ uint32_t h2pack(float a, float b) {
    __half2 h = __floats2half2_rn(a, b);
    return *reinterpret_cast<uint32_t*>(&h);
}

__device__ __forceinline__ __half2 u2h2(uint32_t v) {
    return *reinterpret_cast<__half2*>(&v);
}

#define CP16(dst, src) \
    asm volatile("cp.async.cg.shared.global [%0], [%1], 16;" :: "r"(dst), "l"(src))
#define CP_COMMIT() asm volatile("cp.async.commit_group;")
#define CP_WAIT1()  asm volatile("cp.async.wait_group 1;")
#define CP_WAIT0()  asm volatile("cp.async.wait_group 0;")

// ---------------------------------------------------------------------------
// Pre-convert kernels
// ---------------------------------------------------------------------------
__global__ __launch_bounds__(256) void conv_x(const float* __restrict__ x)
{
    const size_t i = ((size_t)blockIdx.x * 256 + threadIdx.x) * 8;
    float4 a = *reinterpret_cast<const float4*>(x + i);
    float4 b = *reinterpret_cast<const float4*>(x + i + 4);
    uint4 t;
    t.x = h2pack(a.x, a.y); t.y = h2pack(a.z, a.w);
    t.z = h2pack(b.x, b.y); t.w = h2pack(b.z, b.w);
    *reinterpret_cast<uint4*>(g_Xh + i) = t;
}

__global__ __launch_bounds__(256) void conv_w(
    const float* __restrict__ Wq, const float* __restrict__ Wk,
    const float* __restrict__ Wv, const float* __restrict__ Wo)
{
    const size_t gi = ((size_t)blockIdx.x * 256 + threadIdx.x) * 2;
    const int z = (int)(gi >> 20);
    const size_t i = gi & 1048575u;
    if (z < 3) {
        const float* src = (z == 0) ? Wq : (z == 1) ? Wk : Wv;
        float2 v = *reinterpret_cast<const float2*>(src + i);
        const int h = (int)(i >> 16);
        const int d = (int)((i >> 6) & 1023);
        const int k = (int)(i & 63);
        *reinterpret_cast<uint32_t*>(&g_Wh[(size_t)z * DD * DD + (size_t)d * DD + h * 64 + k]) =
            h2pack(v.x, v.y);
    } else {
        float2 v = *reinterpret_cast<const float2*>(Wo + i);
        *reinterpret_cast<uint32_t*>(&g_Woh[i]) = h2pack(v.x, v.y);
    }
}

// ---------------------------------------------------------------------------
// fp16 GEMM: C[128x128], BK=32, 256 thr, warp 64x32, 3-stage cp.async,
// single __syncthreads per k-iteration. (unchanged from best)
// ---------------------------------------------------------------------------
#define APH 40
#define BPH 136
#define AS_BYTES (128 * APH * 2)
#define BS_BYTES (32 * BPH * 2)
#define GEMM_SMEM (3 * (AS_BYTES + BS_BYTES))
#define NKIT (DD / 32)

template<int MODE>
__device__ __forceinline__ void gemm_body(
    const __half* __restrict__ Asrc,
    const __half* __restrict__ Bsrc,
    int m0, int n0g, float* outp)
{
    extern __shared__ __align__(16) char sm[];
    const uint32_t as_b0 = smem_u32(sm);
    const uint32_t bs_b0 = as_b0 + 3 * AS_BYTES;

    const int nloc = n0g & 1023;

    const int tid  = threadIdx.x;
    const int warp = tid >> 5;
    const int lane = tid & 31;
    const int g    = lane >> 2;
    const int tig  = lane & 3;
    const int wm   = (warp & 1) * 64;
    const int wn   = (warp >> 1) * 32;

    const int rA  = (lane & 7) + ((lane >> 3) & 1) * 8;
    const int cA  = ((lane >> 4) & 1) * 8;
    const int rBt = (lane & 7) + ((lane >> 3) & 1) * 8;
    const int cBt = ((lane >> 4) & 1) * 8;

    const int am  = tid & 127;
    const int akh = (tid >> 7) * 16;
    const int bkr = tid >> 3;
    const int bc0 = (tid & 7) * 8;

    const uint32_t aDst = as_b0 + (am * APH + akh) * 2;
    const uint32_t bDst = bs_b0 + (bkr * BPH + bc0) * 2;
    const __half* aSrc = Asrc + (size_t)(m0 + am) * DD + akh;
    const __half* bSrc = Bsrc + (size_t)bkr * DD + nloc + bc0;

    float acc[4][4][4];
    #pragma unroll
    for (int i = 0; i < 4; ++i)
        #pragma unroll
        for (int j = 0; j < 4; ++j)
            #pragma unroll
            for (int l2 = 0; l2 < 4; ++l2) acc[i][j][l2] = 0.f;

    CP16(aDst,                    aSrc);
    CP16(aDst + 16,               aSrc + 8);
    CP16(bDst,                    bSrc);
    CP16(bDst + 128,              bSrc + 64);
    CP_COMMIT();
    CP16(aDst + AS_BYTES,         aSrc + 32);
    CP16(aDst + AS_BYTES + 16,    aSrc + 40);
    CP16(bDst + BS_BYTES,         bSrc + 32 * DD);
    CP16(bDst + BS_BYTES + 128,   bSrc + 32 * DD + 64);
    CP_COMMIT();

    int bc_ = 0;
    int bn_ = 2;

    for (int it = 0; it < NKIT; ++it) {
        if (it + 1 < NKIT) { CP_WAIT1(); } else { CP_WAIT0(); }
        __syncthreads();

        if (it + 2 < NKIT) {
            const uint32_t ab = (uint32_t)bn_ * AS_BYTES;
            const uint32_t bb = (uint32_t)bn_ * BS_BYTES;
            const __half* as2 = aSrc + (it + 2) * 32;
            const __half* bs2 = bSrc + (size_t)(it + 2) * 32 * DD;
            CP16(aDst + ab,       as2);
            CP16(aDst + ab + 16,  as2 + 8);
            CP16(bDst + bb,       bs2);
            CP16(bDst + bb + 128, bs2 + 64);
            CP_COMMIT();
        }

        const uint32_t asb = as_b0 + (uint32_t)bc_ * AS_BYTES;
        const uint32_t bsb = bs_b0 + (uint32_t)bc_ * BS_BYTES;
        #pragma unroll
        for (int kc = 0; kc < 2; ++kc) {
            uint32_t af[4][4];
            #pragma unroll
            for (int mt = 0; mt < 4; ++mt)
                ldsm4(af[mt], asb + ((wm + mt * 16 + rA) * APH + kc * 16 + cA) * 2);
            uint32_t bf[2][4];
            ldsm4t(bf[0], bsb + ((kc * 16 + rBt) * BPH + wn + cBt) * 2);
            ldsm4t(bf[1], bsb + ((kc * 16 + rBt) * BPH + wn + 16 + cBt) * 2);
            #pragma unroll
            for (int mt = 0; mt < 4; ++mt) {
                mma_f16(acc[mt][0], af[mt], bf[0][0], bf[0][1]);
                mma_f16(acc[mt][1], af[mt], bf[0][2], bf[0][3]);
                mma_f16(acc[mt][2], af[mt], bf[1][0], bf[1][1]);
                mma_f16(acc[mt][3], af[mt], bf[1][2], bf[1][3]);
            }
        }

        bc_ = (bc_ == 2) ? 0 : bc_ + 1;
        bn_ = (bn_ == 2) ? 0 : bn_ + 1;
    }

    if (MODE == 0) {
        const int z = n0g >> 10;
        __half* Cout = (z == 0) ? g_Q : (z == 1) ? g_K : g_V;
        const float outsc = (z == 0) ? QSC_F : 1.0f;
        #pragma unroll
        for (int mt = 0; mt < 4; ++mt) {
            #pragma unroll
            for (int nt = 0; nt < 4; ++nt) {
                const int nl = nloc + wn + nt * 8 + 2 * tig;
                const int h = nl >> 6;
                const int k = nl & 63;
                #pragma unroll
                for (int rh = 0; rh < 2; ++rh) {
                    const int m = m0 + wm + mt * 16 + g + rh * 8;
                    const int b = m >> 11;
                    const int s = m & 2047;
                    uint32_t v = h2pack(acc[mt][nt][rh * 2] * outsc, acc[mt][nt][rh * 2 + 1] * outsc);
                    *reinterpret_cast<uint32_t*>(
                        &Cout[(((size_t)(b * HH + h)) * SS + s) * DK + k]) = v;
                }
            }
        }
    } else {
        #pragma unroll
        for (int mt = 0; mt < 4; ++mt) {
            #pragma unroll
            for (int nt = 0; nt < 4; ++nt) {
                const int col = n0g + wn + nt * 8 + 2 * tig;
                #pragma unroll
                for (int rh = 0; rh < 2; ++rh) {
                    const int m = m0 + wm + mt * 16 + g + rh * 8;
                    float2 v = make_float2(acc[mt][nt][rh * 2], acc[mt][nt][rh * 2 + 1]);
                    *reinterpret_cast<float2*>(&outp[(size_t)m * DD + col]) = v;
                }
            }
        }
    }
}

__global__ __launch_bounds__(256, 2) void qkv_gemm_t()
{
    const int n0g = blockIdx.y * 128;
    const int z = n0g >> 10;
    gemm_body<0>(g_Xh, g_Wh + (size_t)z * DD * DD, blockIdx.x * 128, n0g, nullptr);
}

__global__ __launch_bounds__(256, 2) void out_gemm_t(float* __restrict__ out)
{
    gemm_body<1>(g_Ct, g_Woh, blockIdx.x * 128, blockIdx.y * 128, out);
}

// ---------------------------------------------------------------------------
// Flash attention: register P via ex2.f16x2 (exp output IS the A fragment),
// deferred fp16 row-sums (overlap PV mma), 3-stage cp.async, single sync/tile.
// ---------------------------------------------------------------------------
#define FPH 72
#define KVB_BYTES (64 * FPH * 2)
#define FA_SMEM (6 * KVB_BYTES)
#define NTILE (SS / 64)

__global__ __launch_bounds__(256, 2) void flash_attn_t()
{
    extern __shared__ __align__(16) char fsm[];
    __half* KV = reinterpret_cast<__half*>(fsm);
    const uint32_t kv_b = smem_u32(fsm);

    const int tid  = threadIdx.x;
    const int w    = tid >> 5;
    const int lane = tid & 31;
    const int g    = lane >> 2;
    const int tig  = lane & 3;
    const int wr   = w * 16;

    const int rA  = (lane & 7) + ((lane >> 3) & 1) * 8;
    const int cA  = ((lane >> 4) & 1) * 8;
    const int rBn = ((lane >> 4) & 1) * 8 + (lane & 7);
    const int cBn = ((lane >> 3) & 1) * 8;
    const int rBt = (lane & 7) + ((lane >> 3) & 1) * 8;
    const int cBt = ((lane >> 4) & 1) * 8;

    const int q0 = blockIdx.x * 128;
    const int bh = blockIdx.y;
    const __half* Qp = g_Q + (size_t)bh * SS * DK;
    const __half* Kp = g_K + (size_t)bh * SS * DK;
    const __half* Vp = g_V + (size_t)bh * SS * DK;

    // stage Q across K bufs 0+1 (128 rows), read qf, release
    {
        const int qr = tid >> 1;
        const int qc = (tid & 1) * 32;
        const uint4* src = reinterpret_cast<const uint4*>(Qp + (size_t)(q0 + qr) * DK + qc);
        #pragma unroll
        for (int j = 0; j < 4; ++j)
            *reinterpret_cast<uint4*>(&KV[qr * FPH + qc + 8 * j]) = src[j];
    }
    __syncthreads();

    uint32_t qf[4][4];
    #pragma unroll
    for (int kc = 0; kc < 4; ++kc)
        ldsm4(qf[kc], kv_b + ((wr + rA) * FPH + kc * 16 + cA) * 2);
    __syncthreads();

    float of[8][4];
    #pragma unroll
    for (int nt = 0; nt < 8; ++nt)
        #pragma unroll
        for (int i = 0; i < 4; ++i) of[nt][i] = 0.f;
    float mA = -1e30f, mB = -1e30f, lA = 0.f, lB = 0.f;

    const int ls = tid >> 2;
    const int lc = (tid & 3) * 16;
    const uint32_t kDst = kv_b + (ls * FPH + lc) * 2;
    const uint32_t vDst = kv_b + 3 * KVB_BYTES + (ls * FPH + lc) * 2;
    const __half* kSrc = Kp + (size_t)ls * DK + lc;
    const __half* vSrc = Vp + (size_t)ls * DK + lc;

    // prologue: tiles 0,1 -> bufs 0,1
    CP16(kDst,                  kSrc);
    CP16(kDst + 16,             kSrc + 8);
    CP16(vDst,                  vSrc);
    CP16(vDst + 16,             vSrc + 8);
    CP_COMMIT();
    CP16(kDst + KVB_BYTES,      kSrc + 64 * DK);
    CP16(kDst + KVB_BYTES + 16, kSrc + 64 * DK + 8);
    CP16(vDst + KVB_BYTES,      vSrc + 64 * DK);
    CP16(vDst + KVB_BYTES + 16, vSrc + 64 * DK + 8);
    CP_COMMIT();

    int bc_ = 0;
    int bn_ = 2;

    for (int it = 0; it < NTILE; ++it) {
        if (it + 1 < NTILE) { CP_WAIT1(); } else { CP_WAIT0(); }
        __syncthreads();

        if (it + 2 < NTILE) {
            const uint32_t bo = (uint32_t)bn_ * KVB_BYTES;
            const __half* ks2 = kSrc + (size_t)(it + 2) * 64 * DK;
            const __half* vs2 = vSrc + (size_t)(it + 2) * 64 * DK;
            CP16(kDst + bo,      ks2);
            CP16(kDst + bo + 16, ks2 + 8);
            CP16(vDst + bo,      vs2);
            CP16(vDst + bo + 16, vs2 + 8);
            CP_COMMIT();
        }

        const uint32_t ksb = kv_b + (uint32_t)bc_ * KVB_BYTES;
        const uint32_t vsb = kv_b + 3 * KVB_BYTES + (uint32_t)bc_ * KVB_BYTES;

        // ---- S = Q K^T ----
        float sf[8][4];
        #pragma unroll
        for (int nt = 0; nt < 8; ++nt)
            #pragma unroll
            for (int i = 0; i < 4; ++i) sf[nt][i] = 0.f;
        #pragma unroll
        for (int kc = 0; kc < 4; ++kc) {
            #pragma unroll
            for (int ntp = 0; ntp < 4; ++ntp) {
                uint32_t bf[4];
                ldsm4(bf, ksb + ((ntp * 16 + rBn) * FPH + kc * 16 + cBn) * 2);
                mma_f16(sf[2 * ntp + 0], qf[kc], bf[0], bf[1]);
                mma_f16(sf[2 * ntp + 1], qf[kc], bf[2], bf[3]);
            }
        }

        // ---- row max (quad reduction) ----
        float mtA = sf[0][0], mtB = sf[0][2];
        #pragma unroll
        for (int nt = 0; nt < 8; ++nt) {
            mtA = fmaxf(mtA, fmaxf(sf[nt][0], sf[nt][1]));
            mtB = fmaxf(mtB, fmaxf(sf[nt][2], sf[nt][3]));
        }
        mtA = fmaxf(mtA, __shfl_xor_sync(0xffffffffu, mtA, 1));
        mtA = fmaxf(mtA, __shfl_xor_sync(0xffffffffu, mtA, 2));
        mtB = fmaxf(mtB, __shfl_xor_sync(0xffffffffu, mtB, 1));
        mtB = fmaxf(mtB, __shfl_xor_sync(0xffffffffu, mtB, 2));

        const float mnA = fmaxf(mA, mtA);
        const float mnB = fmaxf(mB, mtB);

        // ---- O/l correction (warp-uniform skip) ----
        float corA = 1.f, corB = 1.f;
        const bool keep = __all_sync(0xffffffffu, (mnA == mA) & (mnB == mB));
        if (!keep) {
            corA = fast_ex2(mA - mnA);
            corB = fast_ex2(mB - mnB);
            #pragma unroll
            for (int nt = 0; nt < 8; ++nt) {
                of[nt][0] *= corA; of[nt][1] *= corA;
                of[nt][2] *= corB; of[nt][3] *= corB;
            }
        }
        mA = mnA; mB = mnB;

        // ---- exp via f16x2: output IS the fp16 P fragment pair ----
        uint32_t pA[8], pB[8];
        #pragma unroll
        for (int nt = 0; nt < 8; ++nt) {
            pA[nt] = ex2_h2(h2pack(sf[nt][0] - mnA, sf[nt][1] - mnA));
            pB[nt] = ex2_h2(h2pack(sf[nt][2] - mnB, sf[nt][3] - mnB));
        }

        uint32_t pf[4][4];
        #pragma unroll
        for (int kc = 0; kc < 4; ++kc) {
            pf[kc][0] = pA[2 * kc];
            pf[kc][1] = pB[2 * kc];
            pf[kc][2] = pA[2 * kc + 1];
            pf[kc][3] = pB[2 * kc + 1];
        }

        // ---- O += P V (issue before the sum reduction) ----
        #pragma unroll
        for (int kc = 0; kc < 4; ++kc) {
            #pragma unroll
            for (int ntp = 0; ntp < 4; ++ntp) {
                uint32_t bf[4];
                ldsm4t(bf, vsb + ((kc * 16 + rBt) * FPH + ntp * 16 + cBt) * 2);
                mma_f16(of[2 * ntp + 0], pf[kc], bf[0], bf[1]);
                mma_f16(of[2 * ntp + 1], pf[kc], bf[2], bf[3]);
            }
        }

        // ---- deferred row sums (depth-2 hadd2 tree, f32 finish) ----
        {
            __half2 a0 = __hadd2(__hadd2(u2h2(pA[0]), u2h2(pA[1])),
                                 __hadd2(u2h2(pA[2]), u2h2(pA[3])));
            __half2 a1 = __hadd2(__hadd2(u2h2(pA[4]), u2h2(pA[5])),
                                 __hadd2(u2h2(pA[6]), u2h2(pA[7])));
            __half2 b0 = __hadd2(__hadd2(u2h2(pB[0]), u2h2(pB[1])),
                                 __hadd2(u2h2(pB[2]), u2h2(pB[3])));
            __half2 b1 = __hadd2(__hadd2(u2h2(pB[4]), u2h2(pB[5])),
                                 __hadd2(u2h2(pB[6]), u2h2(pB[7])));
            float2 fa0 = __half22float2(a0), fa1 = __half22float2(a1);
            float2 fb0 = __half22float2(b0), fb1 = __half22float2(b1);
            float sumA = (fa0.x + fa0.y) + (fa1.x + fa1.y);
            float sumB = (fb0.x + fb0.y) + (fb1.x + fb1.y);
            sumA += __shfl_xor_sync(0xffffffffu, sumA, 1);
            sumA += __shfl_xor_sync(0xffffffffu, sumA, 2);
            sumB += __shfl_xor_sync(0xffffffffu, sumB, 1);
            sumB += __shfl_xor_sync(0xffffffffu, sumB, 2);
            lA = lA * corA + sumA;
            lB = lB * corB + sumB;
        }

        bc_ = (bc_ == 2) ? 0 : bc_ + 1;
        bn_ = (bn_ == 2) ? 0 : bn_ + 1;
    }

    // ---- epilogue ----
    {
        const float invA = 1.f / lA;
        const float invB = 1.f / lB;
        const int b = bh >> 4, h = bh & 15;
        const size_t rowA = (size_t)b * SS + q0 + wr + g;
        const size_t rowB = rowA + 8;
        #pragma unroll
        for (int nt = 0; nt < 8; ++nt) {
            const int col = h * 64 + nt * 8 + 2 * tig;
            *reinterpret_cast<uint32_t*>(&g_Ct[rowA * DD + col]) =
                h2pack(of[nt][0] * invA, of[nt][1] * invA);
            *reinterpret_cast<uint32_t*>(&g_Ct[rowB * DD + col]) =
                h2pack(of[nt][2] * invB, of[nt][3] * invB);
        }
    }
}

extern "C" void kernel_launch(void* const* d_in, const int* in_sizes, int n_in,
                              void* d_out, int out_size)
{
    const float* x  = (const float*)d_in[0];
    const float* Wq = (const float*)d_in[1];
    const float* Wk = (const float*)d_in[2];
    const float* Wv = (const float*)d_in[3];
    const float* Wo = (const float*)d_in[4];
    float* out = (float*)d_out;

    (void)in_sizes; (void)n_in; (void)out_size;

    cudaFuncSetAttribute(qkv_gemm_t, cudaFuncAttributeMaxDynamicSharedMemorySize, GEMM_SMEM);
    cudaFuncSetAttribute(out_gemm_t, cudaFuncAttributeMaxDynamicSharedMemorySize, GEMM_SMEM);
    cudaFuncSetAttribute(flash_attn_t, cudaFuncAttributeMaxDynamicSharedMemorySize, FA_SMEM);

    conv_x<<<(M_TOT * DD) / (256 * 8), 256>>>(x);
    conv_w<<<(4 * DD * DD) / (256 * 2), 256>>>(Wq, Wk, Wv, Wo);
    qkv_gemm_t<<<dim3(M_TOT / 128, 24), 256, GEMM_SMEM>>>();
    flash_attn_t<<<dim3(SS / 128, BB * HH), 256, FA_SMEM>>>();
    out_gemm_t<<<dim3(M_TOT / 128, 8), 256, GEMM_SMEM>>>(out);
}